// round 8
// baseline (speedup 1.0000x reference)
#include <cuda_runtime.h>
#include <cuda_bf16.h>

#define VOCAB 32000
#define EMB   256
#define HID   512
#define BATCH 64
#define SEQ   512

typedef unsigned long long ull;

// ------------------------- device scratch (no runtime alloc) ---------------
__device__ float g_xin[(size_t)SEQ * BATCH * HID];     // [s][b][i]
__device__ float g_states[(size_t)SEQ * BATCH * HID];  // [s][b][i]
__device__ float g_feat[BATCH * 2 * HID];              // [b][1024]

// ------------------------- packed fp32x2 helpers ---------------------------
__device__ __forceinline__ void fma2(ull& d, ull a, ull b) {
    asm("fma.rn.f32x2 %0, %1, %2, %0;" : "+l"(d) : "l"(a), "l"(b));
}
__device__ __forceinline__ float2 unpack2(ull v) {
    float lo, hi;
    asm("mov.b64 {%0, %1}, %2;" : "=f"(lo), "=f"(hi) : "l"(v));
    return make_float2(lo, hi);
}
__device__ __forceinline__ ull dup2(float x) {
    ull r;
    asm("mov.b64 %0, {%1, %1};" : "=l"(r) : "f"(x));
    return r;
}
__device__ __forceinline__ unsigned smem_u32(const void* p) {
    unsigned a;
    asm("{ .reg .u64 t; cvta.to.shared.u64 t, %1; cvt.u32.u64 %0, t; }"
        : "=r"(a) : "l"(p));
    return a;
}

// ------------------------- mbarrier primitives -----------------------------
__device__ __forceinline__ void mbar_init(unsigned mbar, unsigned cnt) {
    asm volatile("mbarrier.init.shared.b64 [%0], %1;" :: "r"(mbar), "r"(cnt) : "memory");
}
__device__ __forceinline__ void mbar_expect_tx(unsigned mbar, unsigned bytes) {
    asm volatile("mbarrier.arrive.expect_tx.release.cluster.shared::cta.b64 _, [%0], %1;"
                 :: "r"(mbar), "r"(bytes) : "memory");
}
__device__ __forceinline__ void mbar_arrive_remote(unsigned mbar) {
    asm volatile("mbarrier.arrive.release.cluster.shared::cluster.b64 _, [%0];"
                 :: "r"(mbar) : "memory");
}
__device__ __forceinline__ void mbar_wait_cta(unsigned mbar, unsigned ph) {
    asm volatile(
        "{\n\t.reg .pred P;\n"
        "W0_%=:\n\t"
        "mbarrier.try_wait.parity.shared::cta.b64 P, [%0], %1, 0x989680;\n\t"
        "@P bra.uni W1_%=;\n\t"
        "bra.uni W0_%=;\n"
        "W1_%=:\n\t}"
        :: "r"(mbar), "r"(ph) : "memory");
}
__device__ __forceinline__ void mbar_wait_cluster(unsigned mbar, unsigned ph) {
    asm volatile(
        "{\n\t.reg .pred P;\n"
        "W0_%=:\n\t"
        "mbarrier.try_wait.parity.acquire.cluster.shared::cta.b64 P, [%0], %1, 0x989680;\n\t"
        "@P bra.uni W1_%=;\n\t"
        "bra.uni W0_%=;\n"
        "W1_%=:\n\t}"
        :: "r"(mbar), "r"(ph) : "memory");
}
__device__ __forceinline__ void st_async_f32(unsigned dst, float v, unsigned mbar) {
    asm volatile("st.async.shared::cluster.mbarrier::complete_tx::bytes.b32 [%0], %1, [%2];"
                 :: "r"(dst), "r"(__float_as_uint(v)), "r"(mbar) : "memory");
}

// ===========================================================================
// K1: xin[s][b][i] = dot(emb[X[b,s]], W_ih[i]) + b_ih[i] + b_hh[i]
// GEMM M=32768 (m = s*64+b), N=512, K=256. Tile 64x128, ktile 16.
// ===========================================================================
__global__ void __launch_bounds__(256) k1_xin(
    const int* __restrict__ X, const float* __restrict__ emb,
    const float* __restrict__ W_ih, const float* __restrict__ b_ih,
    const float* __restrict__ b_hh)
{
    __shared__ int rsh[64];
    __shared__ __align__(16) float As[16 * 64];   // [k][m]
    __shared__ __align__(16) float Bs[16 * 128];  // [k][n]
    const int t  = threadIdx.x;
    const int mt = blockIdx.x;            // == s
    const int n0 = blockIdx.y * 128;
    if (t < 64) rsh[t] = X[(size_t)t * SEQ + mt];

    const int tx = t & 31, ty = t >> 5;
    const int ml = t >> 2, kq = (t & 3) * 4;
    const int vb = t >> 1, k8 = (t & 1) * 8;

    ull acc2[4][4];
#pragma unroll
    for (int rp = 0; rp < 4; rp++)
#pragma unroll
        for (int c = 0; c < 4; c++) acc2[rp][c] = 0ull;

    __syncthreads();
    const int arow = rsh[ml];

    for (int k0 = 0; k0 < EMB; k0 += 16) {
        float4 av = *(const float4*)&emb[(size_t)arow * EMB + k0 + kq];
        As[(kq + 0) * 64 + ml] = av.x;
        As[(kq + 1) * 64 + ml] = av.y;
        As[(kq + 2) * 64 + ml] = av.z;
        As[(kq + 3) * 64 + ml] = av.w;
#pragma unroll
        for (int h = 0; h < 2; h++) {
            float4 bv = *(const float4*)&W_ih[(size_t)(n0 + vb) * EMB + k0 + k8 + 4 * h];
            Bs[(k8 + 4 * h + 0) * 128 + vb] = bv.x;
            Bs[(k8 + 4 * h + 1) * 128 + vb] = bv.y;
            Bs[(k8 + 4 * h + 2) * 128 + vb] = bv.z;
            Bs[(k8 + 4 * h + 3) * 128 + vb] = bv.w;
        }
        __syncthreads();
#pragma unroll
        for (int kk = 0; kk < 16; kk++) {
            const ull* ap = (const ull*)&As[kk * 64 + ty * 8];
            ull a0 = ap[0], a1 = ap[1], a2 = ap[2], a3 = ap[3];
            float4 Wv = *(const float4*)&Bs[kk * 128 + tx * 4];
            ull wd[4] = {dup2(Wv.x), dup2(Wv.y), dup2(Wv.z), dup2(Wv.w)};
#pragma unroll
            for (int c = 0; c < 4; c++) {
                fma2(acc2[0][c], a0, wd[c]);
                fma2(acc2[1][c], a1, wd[c]);
                fma2(acc2[2][c], a2, wd[c]);
                fma2(acc2[3][c], a3, wd[c]);
            }
        }
        __syncthreads();
    }

    const int nbase = n0 + tx * 4;
    float bias[4];
#pragma unroll
    for (int c = 0; c < 4; c++) bias[c] = b_ih[nbase + c] + b_hh[nbase + c];
#pragma unroll
    for (int rp = 0; rp < 4; rp++) {
        float2 p0 = unpack2(acc2[rp][0]);
        float2 p1 = unpack2(acc2[rp][1]);
        float2 p2 = unpack2(acc2[rp][2]);
        float2 p3 = unpack2(acc2[rp][3]);
        int bl0 = ty * 8 + 2 * rp;
        float4 o0, o1;
        o0.x = p0.x + bias[0]; o0.y = p1.x + bias[1];
        o0.z = p2.x + bias[2]; o0.w = p3.x + bias[3];
        o1.x = p0.y + bias[0]; o1.y = p1.y + bias[1];
        o1.z = p2.y + bias[2]; o1.w = p3.y + bias[3];
        *(float4*)&g_xin[((size_t)mt * BATCH + bl0) * HID + nbase]     = o0;
        *(float4*)&g_xin[((size_t)mt * BATCH + bl0 + 1) * HID + nbase] = o1;
    }
}

// ===========================================================================
// K2: persistent clustered RNN. 16 clusters x 8 CTAs, 512 threads/CTA.
// W_hh in registers (32 ull/thread). h exchange via st.async + mbarrier
// (full/empty, parity double-buffered) — NO cluster barrier per step.
// Layout: cluster cg -> batches [cg*4,+4); rank -> i-rows [rank*64,+64).
// Thread: lane ip -> rows ip & ip+32; warp jseg (16) -> j in [jseg*32,+32).
// ===========================================================================
struct K2S {
    float hbuf[2 * 4 * 512];   // 16384 B  [parity][b][j]
    float red[16 * 256];       // 16384 B  [jseg][b*64+i]
    ull   full[2];             // offset 32768
    ull   empty[2];            // offset 32784
};
#define HB_OFF   0u
#define FULL_OFF 32768u
#define EMPTY_OFF 32784u
#define TX_BYTES 8192u

__global__ void __launch_bounds__(512, 1) __cluster_dims__(8, 1, 1)
k2_rnn(const float* __restrict__ W_hh)
{
    __shared__ __align__(16) K2S sm;

    const int t = threadIdx.x;
    unsigned rank;
    asm("mov.u32 %0, %%cluster_ctarank;" : "=r"(rank));
    const int cg = blockIdx.x >> 3;
    const int b0 = cg * 4;

    const int ip   = t & 31;     // i-row base (lane)
    const int jseg = t >> 5;     // warp = 32-wide j segment (16 warps)
    const int ob   = t >> 6;     // output batch (t<256)
    const int oi   = t & 63;     // output i (local)
    const int iglob = (int)rank * 64 + oi;

    // ---- W_hh rows in registers: rows (rank*64+ip, +32), j [jseg*32,+32) ----
    ull w0[16], w1[16];
    {
        const ull* wg0 = (const ull*)&W_hh[(size_t)(rank * 64 + ip) * HID + jseg * 32];
        const ull* wg1 = (const ull*)&W_hh[(size_t)(rank * 64 + ip + 32) * HID + jseg * 32];
#pragma unroll
        for (int jj = 0; jj < 16; jj++) { w0[jj] = wg0[jj]; w1[jj] = wg1[jj]; }
    }

    // ---- cluster peer base addresses ----
    unsigned base = smem_u32(&sm);
    unsigned peer[8];
#pragma unroll
    for (int r = 0; r < 8; r++)
        asm("mapa.shared::cluster.u32 %0, %1, %2;"
            : "=r"(peer[r]) : "r"(base), "r"(r));

    // ---- init protocol ----
    if (t == 0) {
        mbar_init(base + FULL_OFF + 0, 1);
        mbar_init(base + FULL_OFF + 8, 1);
        mbar_init(base + EMPTY_OFF + 0, 8);
        mbar_init(base + EMPTY_OFF + 8, 8);
    }
    __syncthreads();
    if (t == 0) {   // pre-arm expect_tx for first use of both full slots
        mbar_expect_tx(base + FULL_OFF + 0, TX_BYTES);
        mbar_expect_tx(base + FULL_OFF + 8, TX_BYTES);
    }
    asm volatile("barrier.cluster.arrive.aligned;" ::: "memory");
    asm volatile("barrier.cluster.wait.aligned;" ::: "memory");
    if (t == 0) {   // pre-arm empty slot 0 and 1 (phase 0) on all peers
#pragma unroll
        for (int r = 0; r < 8; r++) {
            mbar_arrive_remote(peer[r] + EMPTY_OFF + 0);
            mbar_arrive_remote(peer[r] + EMPTY_OFF + 8);
        }
    }

    for (int s = 0; s < SEQ; s++) {
        float xv = 0.f;
        if (t < 256)
            xv = __ldg(&g_xin[((size_t)s * BATCH + b0 + ob) * HID + iglob]);

        float dot = 0.f;
        if (s > 0) {
            const int q = (s - 1) & 1;
            // wait for h(s-1) (8 KB from 8 CTAs incl. self)
            mbar_wait_cta(base + FULL_OFF + q * 8, (unsigned)(((s - 1) >> 1) & 1));

            const float* hb = sm.hbuf + q * 2048;
            ull acc[8];
#pragma unroll
            for (int z = 0; z < 8; z++) acc[z] = 0ull;
#pragma unroll
            for (int z = 0; z < 8; z++) {
#pragma unroll
                for (int b = 0; b < 4; b++) {
                    ulonglong2 h2 =
                        *(const ulonglong2*)&hb[b * 512 + jseg * 32 + z * 4];
                    fma2(acc[b],     w0[2 * z],     h2.x);
                    fma2(acc[4 + b], w1[2 * z],     h2.x);
                    fma2(acc[b],     w0[2 * z + 1], h2.y);
                    fma2(acc[4 + b], w1[2 * z + 1], h2.y);
                }
            }
#pragma unroll
            for (int b = 0; b < 4; b++) {
                float2 pa = unpack2(acc[b]);
                float2 pb = unpack2(acc[4 + b]);
                sm.red[jseg * 256 + b * 64 + ip]      = pa.x + pa.y;
                sm.red[jseg * 256 + b * 64 + ip + 32] = pb.x + pb.y;
            }
            __syncthreads();   // all hbuf reads + red writes done

            if (t == 0) {
                // re-arm full[q] for its next use (step s+1), THEN release
                // producers by signaling done-reading on every peer's empty[q]
                mbar_expect_tx(base + FULL_OFF + q * 8, TX_BYTES);
#pragma unroll
                for (int r = 0; r < 8; r++)
                    mbar_arrive_remote(peer[r] + EMPTY_OFF + q * 8);
            }

            if (t < 256) {
#pragma unroll
                for (int z = 0; z < 16; z++)
                    dot += sm.red[z * 256 + t];
            }
        }

        if (t < 256) {
            float h = tanhf(xv + dot);
            if (s < SEQ - 1) {
                const int p = s & 1;
                // backpressure: slot p free (consumers of step s-2 done)
                mbar_wait_cluster(base + EMPTY_OFF + p * 8, (unsigned)((s >> 1) & 1));
                unsigned boff = (unsigned)((p * 2048 + ob * 512 + iglob) * 4);
#pragma unroll
                for (int r = 0; r < 8; r++)
                    st_async_f32(peer[r] + HB_OFF + boff, h,
                                 peer[r] + FULL_OFF + (unsigned)(p * 8));
            }
            g_states[((size_t)s * BATCH + b0 + ob) * HID + iglob] = h;
        }
    }

    asm volatile("barrier.cluster.arrive.aligned;" ::: "memory");
    asm volatile("barrier.cluster.wait.aligned;" ::: "memory");
}

// ===========================================================================
// K3: attention + feat. One CTA per batch b, 512 threads.
// ===========================================================================
__global__ void __launch_bounds__(512) k3_attn()
{
    __shared__ float lsh[512];
    __shared__ float ash[512];
    __shared__ float red[16];
    const int b = blockIdx.x;
    const int t = threadIdx.x;
    const int lane = t & 31, wid = t >> 5;

    lsh[t] = g_states[((size_t)(SEQ - 1) * BATCH + b) * HID + t];
    __syncthreads();

    for (int s = wid; s < SEQ - 1; s += 16) {
        const float* hs = &g_states[((size_t)s * BATCH + b) * HID];
        float p = 0.f;
#pragma unroll
        for (int m = 0; m < 16; m++)
            p = fmaf(hs[lane + 32 * m], lsh[lane + 32 * m], p);
#pragma unroll
        for (int o = 16; o > 0; o >>= 1) p += __shfl_down_sync(0xffffffffu, p, o);
        if (lane == 0) ash[s] = p;
    }
    __syncthreads();

    float v = (t < SEQ - 1) ? ash[t] : -3.0e38f;
    float mx = v;
#pragma unroll
    for (int o = 16; o > 0; o >>= 1) mx = fmaxf(mx, __shfl_xor_sync(0xffffffffu, mx, o));
    if (lane == 0) red[wid] = mx;
    __syncthreads();
    float m2 = red[0];
#pragma unroll
    for (int i = 1; i < 16; i++) m2 = fmaxf(m2, red[i]);
    __syncthreads();

    float e = (t < SEQ - 1) ? __expf(v - m2) : 0.f;
    float sm = e;
#pragma unroll
    for (int o = 16; o > 0; o >>= 1) sm += __shfl_xor_sync(0xffffffffu, sm, o);
    if (lane == 0) red[wid] = sm;
    __syncthreads();
    float tot = 0.f;
#pragma unroll
    for (int i = 0; i < 16; i++) tot += red[i];
    float inv = 1.f / tot;
    __syncthreads();
    if (t < SEQ - 1) ash[t] = e * inv;
    __syncthreads();

    float ctx = 0.f;
#pragma unroll 4
    for (int s = 0; s < SEQ - 1; s++)
        ctx = fmaf(ash[s], g_states[((size_t)s * BATCH + b) * HID + t], ctx);

    g_feat[b * 1024 + t]       = ctx;
    g_feat[b * 1024 + 512 + t] = lsh[t];
}

// ===========================================================================
// K4: out[b][v] = dot(feat[b], W[v]) + bias[v]. M=64, N=32000, K=1024.
// Tile 32x128, grid (250, 2) = 500 blocks (3.4 waves vs 1.7 before).
// ===========================================================================
__global__ void __launch_bounds__(256) k4_out(
    const float* __restrict__ W, const float* __restrict__ bias,
    float* __restrict__ out)
{
    __shared__ __align__(16) float As[16 * 32];
    __shared__ __align__(16) float Bs[16 * 128];
    const int t  = threadIdx.x;
    const int n0 = blockIdx.x * 128;
    const int m0 = blockIdx.y * 32;
    const int tx = t & 31, ty = t >> 5;
    const int ml = t >> 3, k2 = (t & 7) * 2;
    const int vb = t >> 1, k8 = (t & 1) * 8;

    ull acc2[2][4];
#pragma unroll
    for (int rp = 0; rp < 2; rp++)
#pragma unroll
        for (int c = 0; c < 4; c++) acc2[rp][c] = 0ull;

    for (int k0 = 0; k0 < 2 * HID; k0 += 16) {
        float2 av = *(const float2*)&g_feat[(size_t)(m0 + ml) * 1024 + k0 + k2];
        As[(k2 + 0) * 32 + ml] = av.x;
        As[(k2 + 1) * 32 + ml] = av.y;
#pragma unroll
        for (int h = 0; h < 2; h++) {
            float4 bv = *(const float4*)&W[(size_t)(n0 + vb) * 1024 + k0 + k8 + 4 * h];
            Bs[(k8 + 4 * h + 0) * 128 + vb] = bv.x;
            Bs[(k8 + 4 * h + 1) * 128 + vb] = bv.y;
            Bs[(k8 + 4 * h + 2) * 128 + vb] = bv.z;
            Bs[(k8 + 4 * h + 3) * 128 + vb] = bv.w;
        }
        __syncthreads();
#pragma unroll
        for (int kk = 0; kk < 16; kk++) {
            const ull* ap = (const ull*)&As[kk * 32 + ty * 4];
            ull a0 = ap[0], a1 = ap[1];
            float4 Wv = *(const float4*)&Bs[kk * 128 + tx * 4];
            ull wd[4] = {dup2(Wv.x), dup2(Wv.y), dup2(Wv.z), dup2(Wv.w)};
#pragma unroll
            for (int c = 0; c < 4; c++) {
                fma2(acc2[0][c], a0, wd[c]);
                fma2(acc2[1][c], a1, wd[c]);
            }
        }
        __syncthreads();
    }

    const int nbase = n0 + tx * 4;
    float bv0 = bias[nbase + 0], bv1 = bias[nbase + 1];
    float bv2 = bias[nbase + 2], bv3 = bias[nbase + 3];
#pragma unroll
    for (int rp = 0; rp < 2; rp++) {
        float2 p0 = unpack2(acc2[rp][0]);
        float2 p1 = unpack2(acc2[rp][1]);
        float2 p2 = unpack2(acc2[rp][2]);
        float2 p3 = unpack2(acc2[rp][3]);
        int bb0 = m0 + ty * 4 + 2 * rp;
        float4 o0, o1;
        o0.x = p0.x + bv0; o0.y = p1.x + bv1; o0.z = p2.x + bv2; o0.w = p3.x + bv3;
        o1.x = p0.y + bv0; o1.y = p1.y + bv1; o1.z = p2.y + bv2; o1.w = p3.y + bv3;
        *(float4*)&out[(size_t)bb0 * VOCAB + nbase]       = o0;
        *(float4*)&out[(size_t)(bb0 + 1) * VOCAB + nbase] = o1;
    }
}

// ===========================================================================
extern "C" void kernel_launch(void* const* d_in, const int* in_sizes, int n_in,
                              void* d_out, int out_size) {
    (void)in_sizes; (void)n_in; (void)out_size;
    const int*   X    = (const int*)d_in[0];
    const float* emb  = (const float*)d_in[1];
    const float* W_ih = (const float*)d_in[2];
    const float* W_hh = (const float*)d_in[3];
    const float* b_ih = (const float*)d_in[4];
    const float* b_hh = (const float*)d_in[5];
    const float* W    = (const float*)d_in[6];
    const float* bias = (const float*)d_in[7];
    float* out = (float*)d_out;

    k1_xin<<<dim3(SEQ, 4), 256>>>(X, emb, W_ih, b_ih, b_hh);
    k2_rnn<<<128, 512>>>(W_hh);
    k3_attn<<<BATCH, 512>>>();
    k4_out<<<dim3(250, 2), 256>>>(W, bias, out);
}

// round 9
// speedup vs baseline: 1.9580x; 1.9580x over previous
#include <cuda_runtime.h>
#include <cuda_bf16.h>

#define VOCAB 32000
#define EMB   256
#define HID   512
#define BATCH 64
#define SEQ   512

typedef unsigned long long ull;

// ------------------------- device scratch (no runtime alloc) ---------------
__device__ float g_xin[(size_t)SEQ * BATCH * HID];     // [s][b][i]
__device__ float g_states[(size_t)SEQ * BATCH * HID];  // [s][b][i]
__device__ float g_feat[BATCH * 2 * HID];              // [b][1024]

// ------------------------- packed fp32x2 helpers ---------------------------
__device__ __forceinline__ void fma2(ull& d, ull a, ull b) {
    asm("fma.rn.f32x2 %0, %1, %2, %0;" : "+l"(d) : "l"(a), "l"(b));
}
__device__ __forceinline__ float2 unpack2(ull v) {
    float lo, hi;
    asm("mov.b64 {%0, %1}, %2;" : "=f"(lo), "=f"(hi) : "l"(v));
    return make_float2(lo, hi);
}
__device__ __forceinline__ ull dup2(float x) {
    ull r;
    asm("mov.b64 %0, {%1, %1};" : "=l"(r) : "f"(x));
    return r;
}
__device__ __forceinline__ unsigned smem_u32(const void* p) {
    unsigned a;
    asm("{ .reg .u64 t; cvta.to.shared.u64 t, %1; cvt.u32.u64 %0, t; }"
        : "=r"(a) : "l"(p));
    return a;
}

// ===========================================================================
// K1: xin[s][b][i] = dot(emb[X[b,s]], W_ih[i]) + b_ih[i] + b_hh[i]
// GEMM M=32768 (m = s*64+b), N=512, K=256. Tile 64x128, ktile 16.
// Double-buffered smem, register prefetch, ONE sync per k-tile.
// ===========================================================================
__global__ void __launch_bounds__(256) k1_xin(
    const int* __restrict__ X, const float* __restrict__ emb,
    const float* __restrict__ W_ih, const float* __restrict__ b_ih,
    const float* __restrict__ b_hh)
{
    __shared__ int rsh[64];
    __shared__ __align__(16) float As[2][16 * 64];   // [buf][k][m]
    __shared__ __align__(16) float Bs[2][16 * 128];  // [buf][k][n]
    const int t  = threadIdx.x;
    const int mt = blockIdx.x;            // == s
    const int n0 = blockIdx.y * 128;
    if (t < 64) rsh[t] = X[(size_t)t * SEQ + mt];

    const int tx = t & 31, ty = t >> 5;
    const int ml = t >> 2, kq = (t & 3) * 4;
    const int vb = t >> 1, k8 = (t & 1) * 8;

    ull acc2[4][4];
#pragma unroll
    for (int rp = 0; rp < 4; rp++)
#pragma unroll
        for (int c = 0; c < 4; c++) acc2[rp][c] = 0ull;

    __syncthreads();
    const int arow = rsh[ml];
    const float* aptr = &emb[(size_t)arow * EMB + kq];
    const float* bptr = &W_ih[(size_t)(n0 + vb) * EMB + k8];

    float4 av  = *(const float4*)&aptr[0];
    float4 bv0 = *(const float4*)&bptr[0];
    float4 bv1 = *(const float4*)&bptr[4];

    for (int it = 0; it < 16; it++) {
        const int buf = it & 1;
        As[buf][(kq + 0) * 64 + ml] = av.x;
        As[buf][(kq + 1) * 64 + ml] = av.y;
        As[buf][(kq + 2) * 64 + ml] = av.z;
        As[buf][(kq + 3) * 64 + ml] = av.w;
        Bs[buf][(k8 + 0) * 128 + vb] = bv0.x;
        Bs[buf][(k8 + 1) * 128 + vb] = bv0.y;
        Bs[buf][(k8 + 2) * 128 + vb] = bv0.z;
        Bs[buf][(k8 + 3) * 128 + vb] = bv0.w;
        Bs[buf][(k8 + 4) * 128 + vb] = bv1.x;
        Bs[buf][(k8 + 5) * 128 + vb] = bv1.y;
        Bs[buf][(k8 + 6) * 128 + vb] = bv1.z;
        Bs[buf][(k8 + 7) * 128 + vb] = bv1.w;
        __syncthreads();
        if (it < 15) {
            const int k0 = (it + 1) * 16;
            av  = *(const float4*)&aptr[k0];
            bv0 = *(const float4*)&bptr[k0];
            bv1 = *(const float4*)&bptr[k0 + 4];
        }
#pragma unroll
        for (int kk = 0; kk < 16; kk++) {
            const ull* ap = (const ull*)&As[buf][kk * 64 + ty * 8];
            ull a0 = ap[0], a1 = ap[1], a2 = ap[2], a3 = ap[3];
            float4 Wv = *(const float4*)&Bs[buf][kk * 128 + tx * 4];
            ull wd[4] = {dup2(Wv.x), dup2(Wv.y), dup2(Wv.z), dup2(Wv.w)};
#pragma unroll
            for (int c = 0; c < 4; c++) {
                fma2(acc2[0][c], a0, wd[c]);
                fma2(acc2[1][c], a1, wd[c]);
                fma2(acc2[2][c], a2, wd[c]);
                fma2(acc2[3][c], a3, wd[c]);
            }
        }
    }

    const int nbase = n0 + tx * 4;
    float bias[4];
#pragma unroll
    for (int c = 0; c < 4; c++) bias[c] = b_ih[nbase + c] + b_hh[nbase + c];
#pragma unroll
    for (int rp = 0; rp < 4; rp++) {
        float2 p0 = unpack2(acc2[rp][0]);
        float2 p1 = unpack2(acc2[rp][1]);
        float2 p2 = unpack2(acc2[rp][2]);
        float2 p3 = unpack2(acc2[rp][3]);
        int bl0 = ty * 8 + 2 * rp;
        float4 o0, o1;
        o0.x = p0.x + bias[0]; o0.y = p1.x + bias[1];
        o0.z = p2.x + bias[2]; o0.w = p3.x + bias[3];
        o1.x = p0.y + bias[0]; o1.y = p1.y + bias[1];
        o1.z = p2.y + bias[2]; o1.w = p3.y + bias[3];
        *(float4*)&g_xin[((size_t)mt * BATCH + bl0) * HID + nbase]     = o0;
        *(float4*)&g_xin[((size_t)mt * BATCH + bl0 + 1) * HID + nbase] = o1;
    }
}

// ===========================================================================
// K2: persistent clustered RNN. 16 clusters x 8 CTAs, 512 threads (16 warps).
// W_hh in registers (32 ull/thread). h exchange: plain st.shared::cluster to
// all 8 peer parity buffers + ONE cluster barrier per step (proven R7 design,
// now with 2x warps for latency hiding and half-length serial chains).
// Cluster cg -> batches [cg*4,+4); rank -> i-rows [rank*64,+64).
// Thread: lane ip -> rows ip & ip+32; warp jseg (16) -> j in [jseg*32,+32).
// ===========================================================================
__global__ void __launch_bounds__(512, 1) __cluster_dims__(8, 1, 1)
k2_rnn(const float* __restrict__ W_hh)
{
    __shared__ __align__(16) float hbuf[2 * 4 * 512];  // [parity][b][j]
    __shared__ float red[16 * 256];                    // [jseg][b*64+i]

    const int t = threadIdx.x;
    unsigned rank;
    asm("mov.u32 %0, %%cluster_ctarank;" : "=r"(rank));
    const int cg = blockIdx.x >> 3;
    const int b0 = cg * 4;

    const int ip   = t & 31;     // i-row base (lane)
    const int jseg = t >> 5;     // warp = 32-wide j segment (16 warps)
    const int ob   = t >> 6;     // output batch (valid for t<256)
    const int oi   = t & 63;     // output i (local)
    const int iglob = (int)rank * 64 + oi;

    // ---- W_hh rows in registers: rows (rank*64+ip, +32), j [jseg*32,+32) ----
    ull w0[16], w1[16];
    {
        const ull* wg0 = (const ull*)&W_hh[(size_t)(rank * 64 + ip) * HID + jseg * 32];
        const ull* wg1 = (const ull*)&W_hh[(size_t)(rank * 64 + ip + 32) * HID + jseg * 32];
#pragma unroll
        for (int jj = 0; jj < 16; jj++) { w0[jj] = wg0[jj]; w1[jj] = wg1[jj]; }
    }

    // peer base addresses of hbuf (DSMEM)
    unsigned hb32 = smem_u32(hbuf);
    unsigned peer[8];
#pragma unroll
    for (int r = 0; r < 8; r++)
        asm("mapa.shared::cluster.u32 %0, %1, %2;"
            : "=r"(peer[r]) : "r"(hb32), "r"(r));

    // all cluster smem live before first DSMEM push
    asm volatile("barrier.cluster.arrive.aligned;" ::: "memory");
    asm volatile("barrier.cluster.wait.aligned;" ::: "memory");

    for (int s = 0; s < SEQ; s++) {
        float xv = 0.f;
        if (t < 256)
            xv = __ldg(&g_xin[((size_t)s * BATCH + b0 + ob) * HID + iglob]);

        float dot = 0.f;
        if (s > 0) {
            const float* hb = hbuf + ((s - 1) & 1) * 2048;
            ull acc[8];
#pragma unroll
            for (int z = 0; z < 8; z++) acc[z] = 0ull;
#pragma unroll
            for (int z = 0; z < 8; z++) {
#pragma unroll
                for (int b = 0; b < 4; b++) {
                    // broadcast LDS.128: h[b][jseg*32 + 4z .. +3]
                    ulonglong2 h2 =
                        *(const ulonglong2*)&hb[b * 512 + jseg * 32 + z * 4];
                    fma2(acc[b],     w0[2 * z],     h2.x);
                    fma2(acc[4 + b], w1[2 * z],     h2.x);
                    fma2(acc[b],     w0[2 * z + 1], h2.y);
                    fma2(acc[4 + b], w1[2 * z + 1], h2.y);
                }
            }
#pragma unroll
            for (int b = 0; b < 4; b++) {
                float2 pa = unpack2(acc[b]);
                float2 pb = unpack2(acc[4 + b]);
                red[jseg * 256 + b * 64 + ip]      = pa.x + pa.y;
                red[jseg * 256 + b * 64 + ip + 32] = pb.x + pb.y;
            }
            __syncthreads();
            if (t < 256) {
                float d0 = 0.f, d1 = 0.f;   // two chains, shorter latency
#pragma unroll
                for (int z = 0; z < 8; z++) {
                    d0 += red[(2 * z) * 256 + t];
                    d1 += red[(2 * z + 1) * 256 + t];
                }
                dot = d0 + d1;
            }
        }

        if (t < 256) {
            float h = tanhf(xv + dot);
            if (s < SEQ - 1) {
                unsigned boff = (unsigned)(((s & 1) * 2048 + ob * 512 + iglob) * 4);
#pragma unroll
                for (int r = 0; r < 8; r++)
                    asm volatile("st.shared::cluster.f32 [%0], %1;"
                                 :: "r"(peer[r] + boff), "f"(h) : "memory");
            }
            asm volatile("barrier.cluster.arrive.aligned;" ::: "memory");
            g_states[((size_t)s * BATCH + b0 + ob) * HID + iglob] = h;
        } else {
            asm volatile("barrier.cluster.arrive.aligned;" ::: "memory");
        }
        asm volatile("barrier.cluster.wait.aligned;" ::: "memory");
    }
}

// ===========================================================================
// K3: attention + feat. One CTA per batch b, 512 threads.
// ===========================================================================
__global__ void __launch_bounds__(512) k3_attn()
{
    __shared__ float lsh[512];
    __shared__ float ash[512];
    __shared__ float red[16];
    const int b = blockIdx.x;
    const int t = threadIdx.x;
    const int lane = t & 31, wid = t >> 5;

    lsh[t] = g_states[((size_t)(SEQ - 1) * BATCH + b) * HID + t];
    __syncthreads();

    for (int s = wid; s < SEQ - 1; s += 16) {
        const float* hs = &g_states[((size_t)s * BATCH + b) * HID];
        float p = 0.f;
#pragma unroll
        for (int m = 0; m < 16; m++)
            p = fmaf(hs[lane + 32 * m], lsh[lane + 32 * m], p);
#pragma unroll
        for (int o = 16; o > 0; o >>= 1) p += __shfl_down_sync(0xffffffffu, p, o);
        if (lane == 0) ash[s] = p;
    }
    __syncthreads();

    float v = (t < SEQ - 1) ? ash[t] : -3.0e38f;
    float mx = v;
#pragma unroll
    for (int o = 16; o > 0; o >>= 1) mx = fmaxf(mx, __shfl_xor_sync(0xffffffffu, mx, o));
    if (lane == 0) red[wid] = mx;
    __syncthreads();
    float m2 = red[0];
#pragma unroll
    for (int i = 1; i < 16; i++) m2 = fmaxf(m2, red[i]);
    __syncthreads();

    float e = (t < SEQ - 1) ? __expf(v - m2) : 0.f;
    float sm = e;
#pragma unroll
    for (int o = 16; o > 0; o >>= 1) sm += __shfl_xor_sync(0xffffffffu, sm, o);
    if (lane == 0) red[wid] = sm;
    __syncthreads();
    float tot = 0.f;
#pragma unroll
    for (int i = 0; i < 16; i++) tot += red[i];
    float inv = 1.f / tot;
    __syncthreads();
    if (t < SEQ - 1) ash[t] = e * inv;
    __syncthreads();

    float ctx = 0.f;
#pragma unroll 4
    for (int s = 0; s < SEQ - 1; s++)
        ctx = fmaf(ash[s], g_states[((size_t)s * BATCH + b) * HID + t], ctx);

    g_feat[b * 1024 + t]       = ctx;
    g_feat[b * 1024 + 512 + t] = lsh[t];
}

// ===========================================================================
// K4: out[b][v] = dot(feat[b], W[v]) + bias[v]. M=64, N=32000, K=1024.
// Tile 64x128 (R7 config), double-buffered, one sync per k-tile. grid = 250.
// ===========================================================================
__global__ void __launch_bounds__(256) k4_out(
    const float* __restrict__ W, const float* __restrict__ bias,
    float* __restrict__ out)
{
    __shared__ __align__(16) float As[2][16 * 64];
    __shared__ __align__(16) float Bs[2][16 * 128];
    const int t  = threadIdx.x;
    const int n0 = blockIdx.x * 128;
    const int tx = t & 31, ty = t >> 5;
    const int ml = t >> 2, kq = (t & 3) * 4;
    const int vb = t >> 1, k8 = (t & 1) * 8;

    ull acc2[4][4];
#pragma unroll
    for (int rp = 0; rp < 4; rp++)
#pragma unroll
        for (int c = 0; c < 4; c++) acc2[rp][c] = 0ull;

    const float* aptr = &g_feat[(size_t)ml * 1024 + kq];
    const float* bptr = &W[(size_t)(n0 + vb) * 1024 + k8];

    float4 av  = *(const float4*)&aptr[0];
    float4 bv0 = *(const float4*)&bptr[0];
    float4 bv1 = *(const float4*)&bptr[4];

    for (int it = 0; it < 64; it++) {
        const int buf = it & 1;
        As[buf][(kq + 0) * 64 + ml] = av.x;
        As[buf][(kq + 1) * 64 + ml] = av.y;
        As[buf][(kq + 2) * 64 + ml] = av.z;
        As[buf][(kq + 3) * 64 + ml] = av.w;
        Bs[buf][(k8 + 0) * 128 + vb] = bv0.x;
        Bs[buf][(k8 + 1) * 128 + vb] = bv0.y;
        Bs[buf][(k8 + 2) * 128 + vb] = bv0.z;
        Bs[buf][(k8 + 3) * 128 + vb] = bv0.w;
        Bs[buf][(k8 + 4) * 128 + vb] = bv1.x;
        Bs[buf][(k8 + 5) * 128 + vb] = bv1.y;
        Bs[buf][(k8 + 6) * 128 + vb] = bv1.z;
        Bs[buf][(k8 + 7) * 128 + vb] = bv1.w;
        __syncthreads();
        if (it < 63) {
            const int k0 = (it + 1) * 16;
            av  = *(const float4*)&aptr[k0];
            bv0 = *(const float4*)&bptr[k0];
            bv1 = *(const float4*)&bptr[k0 + 4];
        }
#pragma unroll
        for (int kk = 0; kk < 16; kk++) {
            const ull* ap = (const ull*)&As[buf][kk * 64 + ty * 8];
            ull a0 = ap[0], a1 = ap[1], a2 = ap[2], a3 = ap[3];
            float4 Wv = *(const float4*)&Bs[buf][kk * 128 + tx * 4];
            ull wd[4] = {dup2(Wv.x), dup2(Wv.y), dup2(Wv.z), dup2(Wv.w)};
#pragma unroll
            for (int c = 0; c < 4; c++) {
                fma2(acc2[0][c], a0, wd[c]);
                fma2(acc2[1][c], a1, wd[c]);
                fma2(acc2[2][c], a2, wd[c]);
                fma2(acc2[3][c], a3, wd[c]);
            }
        }
    }

    const int nbase = n0 + tx * 4;
    float bv_0 = bias[nbase + 0], bv_1 = bias[nbase + 1];
    float bv_2 = bias[nbase + 2], bv_3 = bias[nbase + 3];
#pragma unroll
    for (int rp = 0; rp < 4; rp++) {
        float2 p0 = unpack2(acc2[rp][0]);
        float2 p1 = unpack2(acc2[rp][1]);
        float2 p2 = unpack2(acc2[rp][2]);
        float2 p3 = unpack2(acc2[rp][3]);
        int bb0 = ty * 8 + 2 * rp;
        float4 o0, o1;
        o0.x = p0.x + bv_0; o0.y = p1.x + bv_1; o0.z = p2.x + bv_2; o0.w = p3.x + bv_3;
        o1.x = p0.y + bv_0; o1.y = p1.y + bv_1; o1.z = p2.y + bv_2; o1.w = p3.y + bv_3;
        *(float4*)&out[(size_t)bb0 * VOCAB + nbase]       = o0;
        *(float4*)&out[(size_t)(bb0 + 1) * VOCAB + nbase] = o1;
    }
}

// ===========================================================================
extern "C" void kernel_launch(void* const* d_in, const int* in_sizes, int n_in,
                              void* d_out, int out_size) {
    (void)in_sizes; (void)n_in; (void)out_size;
    const int*   X    = (const int*)d_in[0];
    const float* emb  = (const float*)d_in[1];
    const float* W_ih = (const float*)d_in[2];
    const float* W_hh = (const float*)d_in[3];
    const float* b_ih = (const float*)d_in[4];
    const float* b_hh = (const float*)d_in[5];
    const float* W    = (const float*)d_in[6];
    const float* bias = (const float*)d_in[7];
    float* out = (float*)d_out;

    k1_xin<<<dim3(SEQ, 4), 256>>>(X, emb, W_ih, b_ih, b_hh);
    k2_rnn<<<128, 512>>>(W_hh);
    k3_attn<<<BATCH, 512>>>();
    k4_out<<<VOCAB / 128, 256>>>(W, bias, out);
}